// round 1
// baseline (speedup 1.0000x reference)
#include <cuda_runtime.h>

#define NN 100000
#define NE 1600000
#define NG 1000
#define NBLK 98   // ceil(NN/1024)

// ---- static scratch (no allocations allowed) ----
__device__ int   g_cnt[2][NN];
__device__ int   g_off[2][NN + 1];
__device__ int   g_cur[2][NN];
__device__ int   g_src[2][NE];
__device__ int   g_bsum[2][NBLK];
__device__ float g_h[NN * 32];

// ================= CSR build =================

__global__ void k_init(float* __restrict__ out, const float* __restrict__ lin_b) {
    int i = blockIdx.x * blockDim.x + threadIdx.x;
    if (i < NG) out[i] = lin_b[0];
    if (i < NN) { g_cnt[0][i] = 0; g_cnt[1][i] = 0; }
}

__global__ void k_hist(const int* __restrict__ el, const int* __restrict__ eg) {
    int e = blockIdx.x * blockDim.x + threadIdx.x;
    if (e >= NE) return;
    const int* ei = blockIdx.y ? eg : el;
    atomicAdd(&g_cnt[blockIdx.y][ei[NE + e]], 1);
}

__global__ void k_scan1() {
    __shared__ int sm[1024];
    int se = blockIdx.y;
    int i = blockIdx.x * 1024 + threadIdx.x;
    sm[threadIdx.x] = (i < NN) ? g_cnt[se][i] : 0;
    __syncthreads();
    for (int st = 512; st > 0; st >>= 1) {
        if (threadIdx.x < st) sm[threadIdx.x] += sm[threadIdx.x + st];
        __syncthreads();
    }
    if (threadIdx.x == 0) g_bsum[se][blockIdx.x] = sm[0];
}

__global__ void k_scan2() {
    int se = blockIdx.x;
    if (threadIdx.x == 0) {
        int acc = 0;
        for (int b = 0; b < NBLK; b++) { int v = g_bsum[se][b]; g_bsum[se][b] = acc; acc += v; }
    }
}

__global__ void k_scan3() {
    __shared__ int sm[1024];
    int se = blockIdx.y;
    int i = blockIdx.x * 1024 + threadIdx.x;
    int v = (i < NN) ? g_cnt[se][i] : 0;
    sm[threadIdx.x] = v;
    __syncthreads();
    for (int st = 1; st < 1024; st <<= 1) {
        int t = (threadIdx.x >= st) ? sm[threadIdx.x - st] : 0;
        __syncthreads();
        sm[threadIdx.x] += t;
        __syncthreads();
    }
    if (i < NN) {
        int excl = g_bsum[se][blockIdx.x] + sm[threadIdx.x] - v;
        g_off[se][i] = excl;
        g_cur[se][i] = excl;
        if (i == NN - 1) g_off[se][NN] = excl + v;
    }
}

__global__ void k_fill(const int* __restrict__ el, const int* __restrict__ eg) {
    int e = blockIdx.x * blockDim.x + threadIdx.x;
    if (e >= NE) return;
    const int* ei = blockIdx.y ? eg : el;
    int src = ei[e], dst = ei[NE + e];
    g_src[blockIdx.y][atomicAdd(&g_cur[blockIdx.y][dst], 1)] = src;
}

// ================= fused MLP helpers (warp = node, lane = out channel) =================

// input: 64 channels as float2 per lane (channels 2*lane, 2*lane+1)
__device__ __forceinline__ float mlp_f2(const float* __restrict__ W1, const float* __restrict__ B1,
                                        const float* __restrict__ W2, const float* __restrict__ B2,
                                        float2 in, int lane) {
    float t = B1[lane];
#pragma unroll
    for (int k = 0; k < 32; k++) {
        float ax = __shfl_sync(0xffffffffu, in.x, k);
        float ay = __shfl_sync(0xffffffffu, in.y, k);
        t = fmaf(ax, W1[(2 * k) * 32 + lane], t);
        t = fmaf(ay, W1[(2 * k + 1) * 32 + lane], t);
    }
    t = fmaxf(t, 0.f);
    float u = B2[lane];
#pragma unroll
    for (int k = 0; k < 32; k++)
        u = fmaf(__shfl_sync(0xffffffffu, t, k), W2[k * 32 + lane], u);
    return u;
}

// input: 64 channels as two scalar halves (channel lane, channel lane+32)
__device__ __forceinline__ float mlp_ss(const float* __restrict__ W1, const float* __restrict__ B1,
                                        const float* __restrict__ W2, const float* __restrict__ B2,
                                        float in0, float in1, int lane) {
    float t = B1[lane];
#pragma unroll
    for (int k = 0; k < 32; k++)
        t = fmaf(__shfl_sync(0xffffffffu, in0, k), W1[k * 32 + lane], t);
#pragma unroll
    for (int k = 0; k < 32; k++)
        t = fmaf(__shfl_sync(0xffffffffu, in1, k), W1[(k + 32) * 32 + lane], t);
    t = fmaxf(t, 0.f);
    float u = B2[lane];
#pragma unroll
    for (int k = 0; k < 32; k++)
        u = fmaf(__shfl_sync(0xffffffffu, t, k), W2[k * 32 + lane], u);
    return u;
}

// input: 32 channels, one per lane
__device__ __forceinline__ float mlp_s(const float* __restrict__ W1, const float* __restrict__ B1,
                                       const float* __restrict__ W2, const float* __restrict__ B2,
                                       float in, int lane) {
    float t = B1[lane];
#pragma unroll
    for (int k = 0; k < 32; k++)
        t = fmaf(__shfl_sync(0xffffffffu, in, k), W1[k * 32 + lane], t);
    t = fmaxf(t, 0.f);
    float u = B2[lane];
#pragma unroll
    for (int k = 0; k < 32; k++)
        u = fmaf(__shfl_sync(0xffffffffu, t, k), W2[k * 32 + lane], u);
    return u;
}

// ================= layer 1: GIN(c11,local) & GIN(c12,global) & m1 fused =================

__global__ __launch_bounds__(256) void k_layer1(
    const float* __restrict__ x,
    const float* __restrict__ w11a, const float* __restrict__ b11a,
    const float* __restrict__ w11b, const float* __restrict__ b11b,
    const float* __restrict__ w12a, const float* __restrict__ b12a,
    const float* __restrict__ w12b, const float* __restrict__ b12b,
    const float* __restrict__ m1a,  const float* __restrict__ m1ab,
    const float* __restrict__ m1b,  const float* __restrict__ m1bb)
{
    __shared__ float s11a[2048], s11b[1024], s12a[2048], s12b[1024], sm1a[2048], sm1b[1024];
    __shared__ float sb[6][32];
    for (int t = threadIdx.x; t < 2048; t += 256) { s11a[t] = w11a[t]; s12a[t] = w12a[t]; sm1a[t] = m1a[t]; }
    for (int t = threadIdx.x; t < 1024; t += 256) { s11b[t] = w11b[t]; s12b[t] = w12b[t]; sm1b[t] = m1b[t]; }
    if (threadIdx.x < 32) {
        sb[0][threadIdx.x] = b11a[threadIdx.x]; sb[1][threadIdx.x] = b11b[threadIdx.x];
        sb[2][threadIdx.x] = b12a[threadIdx.x]; sb[3][threadIdx.x] = b12b[threadIdx.x];
        sb[4][threadIdx.x] = m1ab[threadIdx.x]; sb[5][threadIdx.x] = m1bb[threadIdx.x];
    }
    __syncthreads();

    int gw = (blockIdx.x * 256 + threadIdx.x) >> 5;
    int lane = threadIdx.x & 31;
    if (gw >= NN) return;

    const float2* __restrict__ x2p = (const float2*)x;
    float2 a = x2p[gw * 32 + lane];
    float2 accl = make_float2(0.f, 0.f), accg = make_float2(0.f, 0.f);

#pragma unroll
    for (int set = 0; set < 2; set++) {
        int b = g_off[set][gw], e = g_off[set][gw + 1];
        float2 acc = make_float2(0.f, 0.f);
        for (int base = b; base < e; base += 32) {
            int n = min(32, e - base);
            int sidx = (lane < n) ? g_src[set][base + lane] : 0;
            for (int kk = 0; kk < n; kk++) {
                int sv = __shfl_sync(0xffffffffu, sidx, kk);
                float2 v = x2p[sv * 32 + lane];
                acc.x += v.x; acc.y += v.y;
            }
        }
        if (set == 0) accl = acc; else accg = acc;
    }

    float2 in1 = make_float2(a.x + accl.x, a.y + accl.y);
    float2 in2 = make_float2(a.x + accg.x, a.y + accg.y);
    float x1v = mlp_f2(s11a, sb[0], s11b, sb[1], in1, lane);
    float x2v = mlp_f2(s12a, sb[2], s12b, sb[3], in2, lane);
    float hv  = mlp_ss(sm1a, sb[4], sm1b, sb[5], x1v, x2v, lane);
    g_h[gw * 32 + lane] = hv;
}

// ================= layer 2: GIN(c21,local) & GIN(c22,global) & m2 & pool & linear fused =================

__global__ __launch_bounds__(256) void k_layer2(
    const int* __restrict__ batch, float* __restrict__ out,
    const float* __restrict__ w21a, const float* __restrict__ b21a,
    const float* __restrict__ w21b, const float* __restrict__ b21b,
    const float* __restrict__ w22a, const float* __restrict__ b22a,
    const float* __restrict__ w22b, const float* __restrict__ b22b,
    const float* __restrict__ m2a,  const float* __restrict__ m2ab,
    const float* __restrict__ m2b,  const float* __restrict__ m2bb,
    const float* __restrict__ linW)
{
    __shared__ float s21a[1024], s21b[1024], s22a[1024], s22b[1024], sm2a[2048], sm2b[1024];
    __shared__ float sb[6][32], slin[32];
    for (int t = threadIdx.x; t < 2048; t += 256) sm2a[t] = m2a[t];
    for (int t = threadIdx.x; t < 1024; t += 256) {
        s21a[t] = w21a[t]; s21b[t] = w21b[t];
        s22a[t] = w22a[t]; s22b[t] = w22b[t];
        sm2b[t] = m2b[t];
    }
    if (threadIdx.x < 32) {
        sb[0][threadIdx.x] = b21a[threadIdx.x]; sb[1][threadIdx.x] = b21b[threadIdx.x];
        sb[2][threadIdx.x] = b22a[threadIdx.x]; sb[3][threadIdx.x] = b22b[threadIdx.x];
        sb[4][threadIdx.x] = m2ab[threadIdx.x]; sb[5][threadIdx.x] = m2bb[threadIdx.x];
        slin[threadIdx.x] = linW[threadIdx.x];
    }
    __syncthreads();

    int gw = (blockIdx.x * 256 + threadIdx.x) >> 5;
    int lane = threadIdx.x & 31;
    if (gw >= NN) return;

    float a = g_h[gw * 32 + lane];
    float accl = 0.f, accg = 0.f;

#pragma unroll
    for (int set = 0; set < 2; set++) {
        int b = g_off[set][gw], e = g_off[set][gw + 1];
        float acc = 0.f;
        for (int base = b; base < e; base += 32) {
            int n = min(32, e - base);
            int sidx = (lane < n) ? g_src[set][base + lane] : 0;
            for (int kk = 0; kk < n; kk++) {
                int sv = __shfl_sync(0xffffffffu, sidx, kk);
                acc += g_h[sv * 32 + lane];
            }
        }
        if (set == 0) accl = acc; else accg = acc;
    }

    float x1v = fmaxf(mlp_s(s21a, sb[0], s21b, sb[1], a + accl, lane), 0.f);
    float x2v = fmaxf(mlp_s(s22a, sb[2], s22b, sb[3], a + accg, lane), 0.f);
    float hv  = mlp_ss(sm2a, sb[4], sm2b, sb[5], x1v, x2v, lane);

    float p = hv * slin[lane];
#pragma unroll
    for (int o = 16; o > 0; o >>= 1) p += __shfl_xor_sync(0xffffffffu, p, o);
    if (lane == 0) atomicAdd(&out[batch[gw]], p);
}

// ================= launch =================

extern "C" void kernel_launch(void* const* d_in, const int* in_sizes, int n_in,
                              void* d_out, int out_size) {
    const float* x     = (const float*)d_in[0];
    const int*   el    = (const int*)d_in[1];
    const int*   eg    = (const int*)d_in[2];
    const int*   batch = (const int*)d_in[3];
    const float* W[26];
    for (int i = 0; i < 26; i++) W[i] = (const float*)d_in[4 + i];
    float* out = (float*)d_out;

    k_init<<<(NN + 255) / 256, 256>>>(out, W[25]);

    dim3 ge((NE + 255) / 256, 2);
    k_hist<<<ge, 256>>>(el, eg);

    dim3 gs(NBLK, 2);
    k_scan1<<<gs, 1024>>>();
    k_scan2<<<2, 32>>>();
    k_scan3<<<gs, 1024>>>();
    k_fill<<<ge, 256>>>(el, eg);

    k_layer1<<<(NN * 32 + 255) / 256, 256>>>(
        x,
        W[0], W[1], W[2], W[3],
        W[4], W[5], W[6], W[7],
        W[8], W[9], W[10], W[11]);

    k_layer2<<<(NN * 32 + 255) / 256, 256>>>(
        batch, out,
        W[12], W[13], W[14], W[15],
        W[16], W[17], W[18], W[19],
        W[20], W[21], W[22], W[23],
        W[24]);
}

// round 2
// speedup vs baseline: 1.0404x; 1.0404x over previous
#include <cuda_runtime.h>

#define NN 100000
#define NE 1600000
#define NG 1000
#define NBLK 98   // ceil(NN/1024)

// ---- static scratch (no allocations allowed) ----
__device__ int   g_cnt[2][NN];
__device__ int   g_off[2][NN + 1];
__device__ int   g_cur[2][NN];
__device__ int   g_src[2][NE];
__device__ int   g_bsum[2][NBLK];
__device__ float g_y1[2][NN * 32];   // layer1 pre-transformed features (x @ c1x_W1)
__device__ float g_y2[2][NN * 32];   // layer2 pre-transformed features (h @ c2x_W1)

// ================= CSR build =================

__global__ void k_init(float* __restrict__ out, const float* __restrict__ lin_b) {
    int i = blockIdx.x * blockDim.x + threadIdx.x;
    if (i < NG) out[i] = lin_b[0];
    if (i < NN) { g_cnt[0][i] = 0; g_cnt[1][i] = 0; }
}

__global__ void k_hist(const int* __restrict__ el, const int* __restrict__ eg) {
    int e = blockIdx.x * blockDim.x + threadIdx.x;
    if (e >= NE) return;
    const int* ei = blockIdx.y ? eg : el;
    atomicAdd(&g_cnt[blockIdx.y][ei[NE + e]], 1);
}

__global__ void k_scan1() {
    __shared__ int sm[1024];
    int se = blockIdx.y;
    int i = blockIdx.x * 1024 + threadIdx.x;
    sm[threadIdx.x] = (i < NN) ? g_cnt[se][i] : 0;
    __syncthreads();
    for (int st = 512; st > 0; st >>= 1) {
        if (threadIdx.x < st) sm[threadIdx.x] += sm[threadIdx.x + st];
        __syncthreads();
    }
    if (threadIdx.x == 0) g_bsum[se][blockIdx.x] = sm[0];
}

__global__ void k_scan2() {
    // parallel exclusive scan of 98 block sums, one block per edge set
    __shared__ int sm[128];
    int se = blockIdx.x;
    int v = (threadIdx.x < NBLK) ? g_bsum[se][threadIdx.x] : 0;
    sm[threadIdx.x] = v;
    __syncthreads();
    for (int st = 1; st < 128; st <<= 1) {
        int t = (threadIdx.x >= st) ? sm[threadIdx.x - st] : 0;
        __syncthreads();
        sm[threadIdx.x] += t;
        __syncthreads();
    }
    if (threadIdx.x < NBLK) g_bsum[se][threadIdx.x] = sm[threadIdx.x] - v;
}

__global__ void k_scan3() {
    __shared__ int sm[1024];
    int se = blockIdx.y;
    int i = blockIdx.x * 1024 + threadIdx.x;
    int v = (i < NN) ? g_cnt[se][i] : 0;
    sm[threadIdx.x] = v;
    __syncthreads();
    for (int st = 1; st < 1024; st <<= 1) {
        int t = (threadIdx.x >= st) ? sm[threadIdx.x - st] : 0;
        __syncthreads();
        sm[threadIdx.x] += t;
        __syncthreads();
    }
    if (i < NN) {
        int excl = g_bsum[se][blockIdx.x] + sm[threadIdx.x] - v;
        g_off[se][i] = excl;
        g_cur[se][i] = excl;
        if (i == NN - 1) g_off[se][NN] = excl + v;
    }
}

__global__ void k_fill(const int* __restrict__ el, const int* __restrict__ eg) {
    int e = blockIdx.x * blockDim.x + threadIdx.x;
    if (e >= NE) return;
    const int* ei = blockIdx.y ? eg : el;
    int src = ei[e], dst = ei[NE + e];
    g_src[blockIdx.y][atomicAdd(&g_cur[blockIdx.y][dst], 1)] = src;
}

// ================= warp matvec helpers (warp = node, lane = out channel) =================

__device__ __forceinline__ float mv32(const float* __restrict__ W, float v, int lane) {
    float u = 0.f;
#pragma unroll
    for (int k = 0; k < 32; k++)
        u = fmaf(__shfl_sync(0xffffffffu, v, k), W[k * 32 + lane], u);
    return u;
}

// two matvecs sharing one broadcast loop (same input vector)
__device__ __forceinline__ void mv32x2(const float* __restrict__ Wa, const float* __restrict__ Wb,
                                       float v, int lane, float& ua, float& ub) {
    ua = 0.f; ub = 0.f;
#pragma unroll
    for (int k = 0; k < 32; k++) {
        float s = __shfl_sync(0xffffffffu, v, k);
        ua = fmaf(s, Wa[k * 32 + lane], ua);
        ub = fmaf(s, Wb[k * 32 + lane], ub);
    }
}

// CSR neighbor-sum gather: acc[lane] = sum over incoming edges of y[src*32+lane]
__device__ __forceinline__ float gather(const float* __restrict__ y, int set, int gw, int lane) {
    int b = g_off[set][gw], e = g_off[set][gw + 1];
    float acc = 0.f;
    for (int base = b; base < e; base += 32) {
        int n = min(32, e - base);
        int sidx = (lane < n) ? g_src[set][base + lane] : 0;
        for (int kk = 0; kk < n; kk++) {
            int sv = __shfl_sync(0xffffffffu, sidx, kk);
            acc += __ldg(&y[sv * 32 + lane]);
        }
    }
    return acc;
}

// ================= precompute: y11 = x @ c11_W1, y12 = x @ c12_W1 =================

__global__ __launch_bounds__(256) void k_pre1(
    const float* __restrict__ x,
    const float* __restrict__ w11a, const float* __restrict__ w12a)
{
    __shared__ float sA[2048], sB[2048];
    for (int t = threadIdx.x; t < 2048; t += 256) { sA[t] = w11a[t]; sB[t] = w12a[t]; }
    __syncthreads();

    int gw = (blockIdx.x * 256 + threadIdx.x) >> 5;
    int lane = threadIdx.x & 31;
    if (gw >= NN) return;

    float2 a = ((const float2*)x)[gw * 32 + lane];   // channels 2*lane, 2*lane+1
    float y1 = 0.f, y2 = 0.f;
#pragma unroll
    for (int k = 0; k < 32; k++) {
        float ax = __shfl_sync(0xffffffffu, a.x, k);  // channel 2k
        float ay = __shfl_sync(0xffffffffu, a.y, k);  // channel 2k+1
        y1 = fmaf(ax, sA[(2 * k) * 32 + lane], y1);
        y1 = fmaf(ay, sA[(2 * k + 1) * 32 + lane], y1);
        y2 = fmaf(ax, sB[(2 * k) * 32 + lane], y2);
        y2 = fmaf(ay, sB[(2 * k + 1) * 32 + lane], y2);
    }
    g_y1[0][gw * 32 + lane] = y1;
    g_y1[1][gw * 32 + lane] = y2;
}

// ================= layer 1: agg(y) + MLP tails + m1 + layer-2 pre-transform =================

__global__ __launch_bounds__(256) void k_layer1(
    const float* __restrict__ b11a, const float* __restrict__ w11b, const float* __restrict__ b11b,
    const float* __restrict__ b12a, const float* __restrict__ w12b, const float* __restrict__ b12b,
    const float* __restrict__ m1a,  const float* __restrict__ m1ab,
    const float* __restrict__ m1b,  const float* __restrict__ m1bb,
    const float* __restrict__ w21a, const float* __restrict__ w22a)
{
    __shared__ float s11b[1024], s12b[1024], sm1a[2048], sm1b[1024], s21a[1024], s22a[1024];
    __shared__ float sb[6][32];
    for (int t = threadIdx.x; t < 2048; t += 256) sm1a[t] = m1a[t];
    for (int t = threadIdx.x; t < 1024; t += 256) {
        s11b[t] = w11b[t]; s12b[t] = w12b[t]; sm1b[t] = m1b[t];
        s21a[t] = w21a[t]; s22a[t] = w22a[t];
    }
    if (threadIdx.x < 32) {
        sb[0][threadIdx.x] = b11a[threadIdx.x]; sb[1][threadIdx.x] = b11b[threadIdx.x];
        sb[2][threadIdx.x] = b12a[threadIdx.x]; sb[3][threadIdx.x] = b12b[threadIdx.x];
        sb[4][threadIdx.x] = m1ab[threadIdx.x]; sb[5][threadIdx.x] = m1bb[threadIdx.x];
    }
    __syncthreads();

    int gw = (blockIdx.x * 256 + threadIdx.x) >> 5;
    int lane = threadIdx.x & 31;
    if (gw >= NN) return;

    float a1 = g_y1[0][gw * 32 + lane];
    float a2 = g_y1[1][gw * 32 + lane];
    float acc1 = gather(g_y1[0], 0, gw, lane);
    float acc2 = gather(g_y1[1], 1, gw, lane);

    // GIN MLP tails (first linear already folded into y)
    float t1 = fmaxf(a1 + acc1 + sb[0][lane], 0.f);
    float x1 = mv32(s11b, t1, lane) + sb[1][lane];
    float t2 = fmaxf(a2 + acc2 + sb[2][lane], 0.f);
    float x2 = mv32(s12b, t2, lane) + sb[3][lane];

    // m1: concat(x1,x2) -> 32 -> 32
    float tm = fmaxf(mv32(sm1a, x1, lane) + mv32(sm1a + 1024, x2, lane) + sb[4][lane], 0.f);
    float hv = mv32(sm1b, tm, lane) + sb[5][lane];

    // pre-transform for layer 2 (shared broadcast loop)
    float y21, y22;
    mv32x2(s21a, s22a, hv, lane, y21, y22);
    g_y2[0][gw * 32 + lane] = y21;
    g_y2[1][gw * 32 + lane] = y22;
}

// ================= layer 2: agg(y2) + MLP tails + m2 + pool + linear =================

__global__ __launch_bounds__(256) void k_layer2(
    const int* __restrict__ batch, float* __restrict__ out,
    const float* __restrict__ b21a, const float* __restrict__ w21b, const float* __restrict__ b21b,
    const float* __restrict__ b22a, const float* __restrict__ w22b, const float* __restrict__ b22b,
    const float* __restrict__ m2a,  const float* __restrict__ m2ab,
    const float* __restrict__ m2b,  const float* __restrict__ m2bb,
    const float* __restrict__ linW)
{
    __shared__ float s21b[1024], s22b[1024], sm2a[2048], sm2b[1024];
    __shared__ float sb[6][32], slin[32];
    for (int t = threadIdx.x; t < 2048; t += 256) sm2a[t] = m2a[t];
    for (int t = threadIdx.x; t < 1024; t += 256) {
        s21b[t] = w21b[t]; s22b[t] = w22b[t]; sm2b[t] = m2b[t];
    }
    if (threadIdx.x < 32) {
        sb[0][threadIdx.x] = b21a[threadIdx.x]; sb[1][threadIdx.x] = b21b[threadIdx.x];
        sb[2][threadIdx.x] = b22a[threadIdx.x]; sb[3][threadIdx.x] = b22b[threadIdx.x];
        sb[4][threadIdx.x] = m2ab[threadIdx.x]; sb[5][threadIdx.x] = m2bb[threadIdx.x];
        slin[threadIdx.x] = linW[threadIdx.x];
    }
    __syncthreads();

    int gw = (blockIdx.x * 256 + threadIdx.x) >> 5;
    int lane = threadIdx.x & 31;
    if (gw >= NN) return;

    float a1 = g_y2[0][gw * 32 + lane];
    float a2 = g_y2[1][gw * 32 + lane];
    float acc1 = gather(g_y2[0], 0, gw, lane);
    float acc2 = gather(g_y2[1], 1, gw, lane);

    float t1 = fmaxf(a1 + acc1 + sb[0][lane], 0.f);
    float x1 = fmaxf(mv32(s21b, t1, lane) + sb[1][lane], 0.f);   // outer relu from reference
    float t2 = fmaxf(a2 + acc2 + sb[2][lane], 0.f);
    float x2 = fmaxf(mv32(s22b, t2, lane) + sb[3][lane], 0.f);

    float tm = fmaxf(mv32(sm2a, x1, lane) + mv32(sm2a + 1024, x2, lane) + sb[4][lane], 0.f);
    float hv = mv32(sm2b, tm, lane) + sb[5][lane];

    float p = hv * slin[lane];
#pragma unroll
    for (int o = 16; o > 0; o >>= 1) p += __shfl_xor_sync(0xffffffffu, p, o);
    if (lane == 0) atomicAdd(&out[batch[gw]], p);
}

// ================= launch =================

extern "C" void kernel_launch(void* const* d_in, const int* in_sizes, int n_in,
                              void* d_out, int out_size) {
    const float* x     = (const float*)d_in[0];
    const int*   el    = (const int*)d_in[1];
    const int*   eg    = (const int*)d_in[2];
    const int*   batch = (const int*)d_in[3];
    const float* W[26];
    for (int i = 0; i < 26; i++) W[i] = (const float*)d_in[4 + i];
    float* out = (float*)d_out;

    k_init<<<(NN + 255) / 256, 256>>>(out, W[25]);

    dim3 ge((NE + 255) / 256, 2);
    k_hist<<<ge, 256>>>(el, eg);

    dim3 gs(NBLK, 2);
    k_scan1<<<gs, 1024>>>();
    k_scan2<<<2, 128>>>();
    k_scan3<<<gs, 1024>>>();
    k_fill<<<ge, 256>>>(el, eg);

    const int NODEBLKS = NN * 32 / 256;   // 12500, exact
    k_pre1<<<NODEBLKS, 256>>>(x, W[0], W[4]);

    k_layer1<<<NODEBLKS, 256>>>(
        W[1], W[2], W[3],
        W[5], W[6], W[7],
        W[8], W[9], W[10], W[11],
        W[12], W[16]);

    k_layer2<<<NODEBLKS, 256>>>(
        batch, out,
        W[13], W[14], W[15],
        W[17], W[18], W[19],
        W[20], W[21], W[22], W[23],
        W[24]);
}